// round 13
// baseline (speedup 1.0000x reference)
#include <cuda_runtime.h>
#include <cuda_bf16.h>
#include <cstdint>

#define TLEN 512
#define HID  256
#define EMB  256
#define VOC  32000
#define NROW 2048   // 2 cells * 4H gate rows

// Scratch (static device globals — no runtime allocation; zero-initialized)
__device__ float g_X[TLEN * NROW];           // 4 MB   precomputed x@W_ih^T + biases
__device__ float g_S[TLEN * 2 * HID];        // 1 MB   s_t = [hf, cf]
__device__ float g_part[TLEN * 256];         // per-(row, colblock) partial sumexp (cols 250-255 stay 0)
__device__ float g_rowoff[TLEN];             // per-row log sum exp

__device__ __forceinline__ uint32_t smem_u32(const void* p) {
    return (uint32_t)__cvta_generic_to_shared(p);
}

__device__ __forceinline__ float fast_ex2(float x) {
    float r; asm("ex2.approx.f32 %0, %1;" : "=f"(r) : "f"(x)); return r;
}
__device__ __forceinline__ float fast_rcp(float x) {
    float r; asm("rcp.approx.f32 %0, %1;" : "=f"(r) : "f"(x)); return r;
}
__device__ __forceinline__ float fsig(float x) {
    return fast_rcp(1.f + fast_ex2(-1.4426950408889634f * x));
}
__device__ __forceinline__ float ftanh(float x) {
    return 1.f - 2.f * fast_rcp(1.f + fast_ex2(2.8853900817779268f * x));
}

#define FMA2(acc, a, b) asm("fma.rn.f32x2 %0, %1, %2, %0;" : "+l"(acc) : "l"(a), "l"(b))

// per-warp mbarrier wait (R4/R8-proven form: cta-scope acquire)
__device__ __forceinline__ void mbar_wait(uint32_t mbar, uint32_t par) {
    asm volatile(
        "{\n\t.reg .pred P;\n\t"
        "WAITLP_%=:\n\t"
        "mbarrier.try_wait.parity.acquire.cta.shared::cta.b64 P, [%0], %1, 0x989680;\n\t"
        "@P bra.uni WAITDN_%=;\n\t"
        "bra.uni WAITLP_%=;\n\t"
        "WAITDN_%=:\n\t}"
        :: "r"(mbar), "r"(par) : "memory");
}

#define LDSM4(r0, r1, r2, r3, addr) \
    asm volatile("ldmatrix.sync.aligned.m8n8.x4.shared.b16 {%0,%1,%2,%3}, [%4];" \
        : "=r"(r0), "=r"(r1), "=r"(r2), "=r"(r3) : "r"(addr))

// ---------------------------------------------------------------------------
// nop kernel: keep the ncu capture slot on k3a_gemm (launch idx 3)
// ---------------------------------------------------------------------------
__global__ void knop1() {}

// ---------------------------------------------------------------------------
// K1: X[t][row] = emb[token_t] . w_ih[row] + b_ih[row] + b_hh[row]
// ---------------------------------------------------------------------------
__global__ __launch_bounds__(256) void k1_precompute(
    const float* __restrict__ emb_table, const int* __restrict__ target,
    const float* __restrict__ wihf, const float* __restrict__ bihf, const float* __restrict__ bhhf,
    const float* __restrict__ wihb, const float* __restrict__ bihb, const float* __restrict__ bhhb)
{
    __shared__ float se[32][EMB];
    const int tblk = blockIdx.x * 32;
    const int rblk = blockIdx.y * 128;

    for (int i = threadIdx.x; i < 32 * EMB; i += 256) {
        int tt = i >> 8;
        int k  = i & 255;
        int t  = tblk + tt;
        int tok = (t == 0) ? 0 : target[t - 1];   // teacher forcing, SOS=0
        se[tt][k] = emb_table[(size_t)tok * EMB + k];
    }
    __syncthreads();

    const int row_l = threadIdx.x & 127;
    const int th    = threadIdx.x >> 7;
    const int row   = rblk + row_l;

    const float* w;
    float bias;
    if (row < 1024) { w = wihf + (size_t)row * EMB;               bias = bihf[row] + bhhf[row]; }
    else            { int r2 = row - 1024; w = wihb + (size_t)r2 * EMB; bias = bihb[r2] + bhhb[r2]; }

    float acc[16];
#pragma unroll
    for (int i = 0; i < 16; i++) acc[i] = 0.f;

    for (int k = 0; k < EMB; k += 4) {
        float4 wv = *(const float4*)(w + k);
#pragma unroll
        for (int i = 0; i < 16; i++) {
            float4 e = *(const float4*)&se[th * 16 + i][k];
            acc[i] += wv.x * e.x + wv.y * e.y + wv.z * e.z + wv.w * e.w;
        }
    }
#pragma unroll
    for (int i = 0; i < 16; i++) {
        int t = tblk + th * 16 + i;
        g_X[t * NROW + row] = acc[i] + bias;
    }
}

// ---------------------------------------------------------------------------
// K2: sequential bilstm recurrence — EXACTLY the R8-proven kernel.
// ---------------------------------------------------------------------------
__global__ void __cluster_dims__(8, 1, 1) __launch_bounds__(256, 1)
k2_lstm(const float* __restrict__ whhf, const float* __restrict__ whhb,
        float* __restrict__ out_seq)
{
    __shared__ __align__(16) float sh_h[2][264];   // 132-float halves (bank-shift pad)
    __shared__ __align__(8) unsigned long long mbarr[2];

    uint32_t rank;
    asm("mov.u32 %0, %%cluster_ctarank;" : "=r"(rank));
    const int cell = blockIdx.x >> 3;
    const float* whh = cell ? whhb : whhf;

    const int tid   = threadIdx.x;
    const int l     = tid & 31;
    const int wrp   = tid >> 5;
    const int v     = wrp * 4 + (l >> 3);   // local unit 0..31
    const int g     = (l >> 1) & 3;         // gate i,f,g,o
    const int khalf = l & 1;                // K half (128 each)
    const int d     = l & 7;                // this lane's destination CTA rank
    const int unit  = (int)rank * 32 + v;
    const int grow  = g * 256 + unit;

    unsigned long long w[64];
    {
        const float2* wp = (const float2*)(whh + (size_t)grow * HID + khalf * 128);
#pragma unroll
        for (int j = 0; j < 64; j++) {
            float2 x = wp[j];
            asm("mov.b64 %0, {%1, %2};" : "=l"(w[j]) : "f"(x.x), "f"(x.y));
        }
    }

    const uint32_t mb0 = smem_u32(&mbarr[0]);
    const uint32_t mb1 = smem_u32(&mbarr[1]);
    for (int i = tid; i < 264; i += 256) { sh_h[0][i] = 0.f; sh_h[1][i] = 0.f; }
    if (tid == 0) {
        asm volatile("mbarrier.init.shared.b64 [%0], %1;" :: "r"(mb0), "r"(1u) : "memory");
        asm volatile("mbarrier.init.shared.b64 [%0], %1;" :: "r"(mb1), "r"(1u) : "memory");
        asm volatile("fence.mbarrier_init.release.cluster;" ::: "memory");
        asm volatile("mbarrier.arrive.expect_tx.shared.b64 _, [%0], %1;" :: "r"(mb0), "r"(1024u) : "memory");
        asm volatile("mbarrier.arrive.expect_tx.shared.b64 _, [%0], %1;" :: "r"(mb1), "r"(1024u) : "memory");
    }
    __syncthreads();
    asm volatile("barrier.cluster.arrive.aligned;" ::: "memory");
    asm volatile("barrier.cluster.wait.aligned;"   ::: "memory");

    const int pos = unit + ((unit >> 7) << 2);
    uint32_t ra0, ra1, rm0, rm1;
    {
        uint32_t la0 = smem_u32(&sh_h[0][pos]);
        uint32_t la1 = smem_u32(&sh_h[1][pos]);
        asm("mapa.shared::cluster.u32 %0, %1, %2;" : "=r"(ra0) : "r"(la0), "r"(d));
        asm("mapa.shared::cluster.u32 %0, %1, %2;" : "=r"(ra1) : "r"(la1), "r"(d));
        asm("mapa.shared::cluster.u32 %0, %1, %2;" : "=r"(rm0) : "r"(mb0), "r"(d));
        asm("mapa.shared::cluster.u32 %0, %1, %2;" : "=r"(rm1) : "r"(mb1), "r"(d));
    }

    float c_reg = 0.f;
    const int xrow = cell * 1024 + grow;

    for (int t = 0; t < TLEN; t++) {
        const int p = t & 1;
        float xv = __ldg(&g_X[t * NROW + xrow]);

        if (t > 0) {
            uint32_t mb = p ? mb1 : mb0;
            mbar_wait(mb, (uint32_t)(((t - 1) >> 1) & 1));
            if (tid == 0)
                asm volatile("mbarrier.arrive.expect_tx.shared.b64 _, [%0], %1;"
                             :: "r"(mb), "r"(1024u) : "memory");
        }

        const ulonglong2* hp = (const ulonglong2*)&sh_h[p][khalf * 132];
        unsigned long long a0 = 0ULL, a1 = 0ULL, a2 = 0ULL, a3 = 0ULL;
#pragma unroll
        for (int j = 0; j < 32; j += 2) {
            ulonglong2 v0 = hp[j];
            ulonglong2 v1 = hp[j + 1];
            FMA2(a0, w[2 * j + 0], v0.x);
            FMA2(a1, w[2 * j + 1], v0.y);
            FMA2(a2, w[2 * j + 2], v1.x);
            FMA2(a3, w[2 * j + 3], v1.y);
        }
        float lo0, hi0, lo1, hi1, lo2, hi2, lo3, hi3;
        asm("mov.b64 {%0, %1}, %2;" : "=f"(lo0), "=f"(hi0) : "l"(a0));
        asm("mov.b64 {%0, %1}, %2;" : "=f"(lo1), "=f"(hi1) : "l"(a1));
        asm("mov.b64 {%0, %1}, %2;" : "=f"(lo2), "=f"(hi2) : "l"(a2));
        asm("mov.b64 {%0, %1}, %2;" : "=f"(lo3), "=f"(hi3) : "l"(a3));
        float sum = ((lo0 + hi0) + (lo1 + hi1)) + ((lo2 + hi2) + (lo3 + hi3));
        sum += __shfl_xor_sync(0xffffffffu, sum, 1);
        float z = sum + xv;

        float act = (g == 2) ? ftanh(z) : fsig(z);
        const int base = l & ~7;
        float gi = __shfl_sync(0xffffffffu, act, base + 0);
        float gf = __shfl_sync(0xffffffffu, act, base + 2);
        float gg = __shfl_sync(0xffffffffu, act, base + 4);
        float go = __shfl_sync(0xffffffffu, act, base + 6);
        c_reg = gf * c_reg + gi * gg;
        float hv = go * ftanh(c_reg);

        if (t < TLEN - 1) {
            uint32_t ra = ((t + 1) & 1) ? ra1 : ra0;
            uint32_t rm = ((t + 1) & 1) ? rm1 : rm0;
            asm volatile(
                "st.async.shared::cluster.mbarrier::complete_tx::bytes.f32 [%0], %1, [%2];"
                :: "r"(ra), "f"(hv), "r"(rm) : "memory");
        }

        const int lg = l & 7;
        if (cell == 0) {
            if (lg == 1) out_seq[t * 512 + unit] = hv;
            else if (lg == 2) g_S[t * 512 + unit] = hv;
            else if (lg == 3) g_S[t * 512 + 256 + unit] = c_reg;
        } else {
            if (lg == 1) out_seq[t * 512 + 256 + unit] = hv;
        }
    }
}

// ---------------------------------------------------------------------------
// K3a: logits = S @ test_w^T + test_b -> d_out + row sumexp partials.
// NEW staging: one thread per smem row (A rows 0-127 = g_S, B rows 128-255 =
// testw), 4x STS.128/thread (conflict-free: 16B-group = (5r+j) mod 8), and
// ldmatrix.x4 fragment loads (6 LDSM per kk vs 24 LDS.32).
// ---------------------------------------------------------------------------
#define KPAD 40
#define TBUF (256 * KPAD * 2)   // bytes per buffer

__global__ __launch_bounds__(256) void k3a_gemm(
    const float* __restrict__ testw, const float* __restrict__ testb,
    float* __restrict__ out)
{
    __shared__ __nv_bfloat16 sT[2][256][KPAD];   // rows 0-127: A, 128-255: B
    __shared__ float sred[128][4];

    const int tid  = threadIdx.x;
    const int Mb   = blockIdx.x * 128;      // 4 M-blocks, fastest axis
    const int nbq  = blockIdx.y;            // 250 N-blocks, slow axis
    const int Nb   = nbq * 128;
    const int warp = tid >> 5, lane = tid & 31;
    const int wm = warp >> 2, wn = warp & 3;
    const int gq = lane >> 2, tg = lane & 3;

    // this thread's staging row + gmem row pointer
    const float* rowptr = (tid < 128)
        ? (g_S   + (size_t)(Mb + tid) * 512)
        : (testw + (size_t)(Nb + (tid - 128)) * 512);
    __nv_bfloat16* srow = &sT[0][tid][0];

    // ldmatrix per-lane byte offsets (row stride 80 B)
    const uint32_t base_s = smem_u32(&sT[0][0][0]);
    const uint32_t a_off  = (uint32_t)((lane & 15) * 80 + ((lane & 16) ? 16 : 0));
    const uint32_t b_off  = (uint32_t)(((lane & 7) + ((lane & 16) ? 8 : 0)) * 80 + ((lane & 8) ? 16 : 0));
    const uint32_t a_base = base_s + (uint32_t)(wm * 64 * 80) + a_off;
    const uint32_t b_base = base_s + (uint32_t)((128 + wn * 32) * 80) + b_off;

    float acc[4][4][4];
#pragma unroll
    for (int a = 0; a < 4; a++)
#pragma unroll
        for (int b = 0; b < 4; b++)
#pragma unroll
            for (int c = 0; c < 4; c++) acc[a][b][c] = 0.f;

    float4 r[8];
#pragma unroll
    for (int i = 0; i < 8; i++) r[i] = *(const float4*)(rowptr + i * 4);

#define STORE_STAGE(buf)                                                          \
    do {                                                                          \
        __nv_bfloat16* dst = srow + (buf) * (256 * KPAD);                         \
        _Pragma("unroll")                                                         \
        for (int j = 0; j < 4; j++) {                                             \
            __nv_bfloat162 h0 = __floats2bfloat162_rn(r[2*j].x,   r[2*j].y);      \
            __nv_bfloat162 h1 = __floats2bfloat162_rn(r[2*j].z,   r[2*j].w);      \
            __nv_bfloat162 h2 = __floats2bfloat162_rn(r[2*j+1].x, r[2*j+1].y);    \
            __nv_bfloat162 h3 = __floats2bfloat162_rn(r[2*j+1].z, r[2*j+1].w);    \
            uint4 u;                                                              \
            u.x = *(uint32_t*)&h0; u.y = *(uint32_t*)&h1;                         \
            u.z = *(uint32_t*)&h2; u.w = *(uint32_t*)&h3;                         \
            *(uint4*)(dst + j * 8) = u;                                           \
        }                                                                         \
    } while (0)

    STORE_STAGE(0);
    __syncthreads();

    for (int kt = 0; kt < 16; kt++) {
        const int cur = kt & 1;
        if (kt < 15) {
#pragma unroll
            for (int i = 0; i < 8; i++)
                r[i] = *(const float4*)(rowptr + (kt + 1) * 32 + i * 4);
        }
        const uint32_t abuf = a_base + (uint32_t)(cur * TBUF);
        const uint32_t bbuf = b_base + (uint32_t)(cur * TBUF);
#pragma unroll
        for (int kk = 0; kk < 32; kk += 16) {
            uint32_t af[4][4], bf[4][2];
#pragma unroll
            for (int mt = 0; mt < 4; mt++)
                LDSM4(af[mt][0], af[mt][1], af[mt][2], af[mt][3],
                      abuf + (uint32_t)(mt * 1280 + kk * 2));
#pragma unroll
            for (int q = 0; q < 2; q++)
                LDSM4(bf[2*q][0], bf[2*q][1], bf[2*q+1][0], bf[2*q+1][1],
                      bbuf + (uint32_t)(q * 1280 + kk * 2));
#pragma unroll
            for (int mt = 0; mt < 4; mt++)
#pragma unroll
                for (int nt = 0; nt < 4; nt++) {
                    asm("mma.sync.aligned.m16n8k16.row.col.f32.bf16.bf16.f32 "
                        "{%0,%1,%2,%3}, {%4,%5,%6,%7}, {%8,%9}, {%0,%1,%2,%3};"
                        : "+f"(acc[mt][nt][0]), "+f"(acc[mt][nt][1]),
                          "+f"(acc[mt][nt][2]), "+f"(acc[mt][nt][3])
                        : "r"(af[mt][0]), "r"(af[mt][1]), "r"(af[mt][2]), "r"(af[mt][3]),
                          "r"(bf[nt][0]), "r"(bf[nt][1]));
                }
        }
        if (kt < 15) STORE_STAGE(cur ^ 1);
        __syncthreads();
    }
#undef STORE_STAGE

    float esum[8];
#pragma unroll
    for (int i = 0; i < 8; i++) esum[i] = 0.f;

#pragma unroll
    for (int nt = 0; nt < 4; nt++) {
        int n = Nb + wn * 32 + nt * 8 + tg * 2;
        float2 tb = *(const float2*)(testb + n);
#pragma unroll
        for (int mt = 0; mt < 4; mt++) {
            int m0 = Mb + wm * 64 + mt * 16 + gq;
            float2 v0 = make_float2(acc[mt][nt][0] + tb.x, acc[mt][nt][1] + tb.y);
            float2 v1 = make_float2(acc[mt][nt][2] + tb.x, acc[mt][nt][3] + tb.y);
            *(float2*)&out[(size_t)m0 * VOC + n] = v0;
            *(float2*)&out[(size_t)(m0 + 8) * VOC + n] = v1;
            esum[mt * 2 + 0] += __expf(v0.x) + __expf(v0.y);
            esum[mt * 2 + 1] += __expf(v1.x) + __expf(v1.y);
        }
    }
#pragma unroll
    for (int i = 0; i < 8; i++) {
        esum[i] += __shfl_xor_sync(0xffffffffu, esum[i], 1);
        esum[i] += __shfl_xor_sync(0xffffffffu, esum[i], 2);
    }
    if (tg == 0) {
#pragma unroll
        for (int mt = 0; mt < 4; mt++) {
            sred[wm * 64 + mt * 16 + gq][wn]     = esum[mt * 2 + 0];
            sred[wm * 64 + mt * 16 + gq + 8][wn] = esum[mt * 2 + 1];
        }
    }
    __syncthreads();
    if (tid < 128) {
        float s = sred[tid][0] + sred[tid][1] + sred[tid][2] + sred[tid][3];
        g_part[(size_t)(Mb + tid) * 256 + nbq] = s;
    }
}

// ---------------------------------------------------------------------------
// K3b: rowoff[t] = log(sum of partials). One block per row, tree reduce.
// ---------------------------------------------------------------------------
__global__ __launch_bounds__(256) void k3b_reduce()
{
    __shared__ float red[256];
    const int t = blockIdx.x;
    float v = g_part[(size_t)t * 256 + threadIdx.x];
    red[threadIdx.x] = v;
    __syncthreads();
#pragma unroll
    for (int s = 128; s > 0; s >>= 1) {
        if (threadIdx.x < s) red[threadIdx.x] += red[threadIdx.x + s];
        __syncthreads();
    }
    if (threadIdx.x == 0) g_rowoff[t] = logf(red[0]);
}

// ---------------------------------------------------------------------------
// K3c: Pvocab = logits - logZ   (in place on d_out)
// ---------------------------------------------------------------------------
__global__ __launch_bounds__(256) void k3c_finalize(float* __restrict__ out)
{
    size_t i = ((size_t)blockIdx.x * 256 + threadIdx.x) * 4;
    int t = (int)(i / VOC);
    float off = g_rowoff[t];
    float4 v = *(const float4*)&out[i];
    v.x -= off; v.y -= off; v.z -= off; v.w -= off;
    *(float4*)&out[i] = v;
}

// ---------------------------------------------------------------------------
extern "C" void kernel_launch(void* const* d_in, const int* in_sizes, int n_in,
                              void* d_out, int out_size)
{
    const float* emb   = (const float*)d_in[1];
    const float* wihf  = (const float*)d_in[2];
    const float* whhf  = (const float*)d_in[3];
    const float* bihf  = (const float*)d_in[4];
    const float* bhhf  = (const float*)d_in[5];
    const float* wihb  = (const float*)d_in[6];
    const float* whhb  = (const float*)d_in[7];
    const float* bihb  = (const float*)d_in[8];
    const float* bhhb  = (const float*)d_in[9];
    const float* testw = (const float*)d_in[20];
    const float* testb = (const float*)d_in[21];
    const int*   tgt   = (const int*)d_in[22];

    float* out_pv  = (float*)d_out;                       // Pvocab [512, 1, 32000]
    float* out_seq = out_pv + (size_t)TLEN * VOC;         // outputs [512, 512]

    k1_precompute<<<dim3(16, 16), 256>>>(emb, tgt, wihf, bihf, bhhf, wihb, bihb, bhhb);
    knop1<<<1, 32>>>();                                   // ncu slot -> k3a (idx 3)
    k2_lstm<<<16, 256>>>(whhf, whhb, out_seq);
    k3a_gemm<<<dim3(4, 250), 256>>>(testw, testb, out_pv);
    k3b_reduce<<<TLEN, 256>>>();
    k3c_finalize<<<(TLEN * VOC / 4) / 256, 256>>>(out_pv);
}

// round 14
// speedup vs baseline: 1.0479x; 1.0479x over previous
#include <cuda_runtime.h>
#include <cuda_bf16.h>
#include <cstdint>

#define TLEN 512
#define HID  256
#define EMB  256
#define VOC  32000
#define NROW 2048   // 2 cells * 4H gate rows
#define NWORK 112   // worker CTAs (bids 16..127)

// Scratch (static device globals — no runtime allocation; zero-initialized)
__device__ float g_X[TLEN * NROW];           // 4 MB   precomputed x@W_ih^T + biases
__device__ float g_S[TLEN * 2 * HID];        // 1 MB   s_t = [hf, cf]
__device__ float g_part[TLEN * 256];         // per-(row, colblock) sumexp partials (cols 250-255 stay 0)
__device__ unsigned g_scnt[4];               // S progress per 128-step chunk (target 64 warp-arrivals)
__device__ unsigned g_tq[4];                 // GEMM tile queue per chunk (take while < 250)
__device__ unsigned g_tcnt[4];               // GEMM tiles completed per chunk (target 250)
__device__ unsigned g_rq[4];                 // fixup row queue per chunk (take while < 128)

__device__ __forceinline__ uint32_t smem_u32(const void* p) {
    return (uint32_t)__cvta_generic_to_shared(p);
}

__device__ __forceinline__ float fast_ex2(float x) {
    float r; asm("ex2.approx.f32 %0, %1;" : "=f"(r) : "f"(x)); return r;
}
__device__ __forceinline__ float fast_rcp(float x) {
    float r; asm("rcp.approx.f32 %0, %1;" : "=f"(r) : "f"(x)); return r;
}
__device__ __forceinline__ float fsig(float x) {
    return fast_rcp(1.f + fast_ex2(-1.4426950408889634f * x));
}
__device__ __forceinline__ float ftanh(float x) {
    return 1.f - 2.f * fast_rcp(1.f + fast_ex2(2.8853900817779268f * x));
}

#define FMA2(acc, a, b) asm("fma.rn.f32x2 %0, %1, %2, %0;" : "+l"(acc) : "l"(a), "l"(b))

__device__ __forceinline__ void mbar_wait(uint32_t mbar, uint32_t par) {
    asm volatile(
        "{\n\t.reg .pred P;\n\t"
        "WAITLP_%=:\n\t"
        "mbarrier.try_wait.parity.acquire.cta.shared::cta.b64 P, [%0], %1, 0x989680;\n\t"
        "@P bra.uni WAITDN_%=;\n\t"
        "bra.uni WAITLP_%=;\n\t"
        "WAITDN_%=:\n\t}"
        :: "r"(mbar), "r"(par) : "memory");
}

// ---------------------------------------------------------------------------
__global__ void kreset() {
    if (threadIdx.x < 4) {
        g_scnt[threadIdx.x] = 0;
        g_tq[threadIdx.x] = 0;
        g_tcnt[threadIdx.x] = 0;
        g_rq[threadIdx.x] = 0;
    }
}
__global__ void knop1() {}

// ---------------------------------------------------------------------------
// K1: X[t][row] = emb[token_t] . w_ih[row] + b_ih[row] + b_hh[row]
// (separate kernel BEFORE the mega: the recurrence never waits on workers)
// ---------------------------------------------------------------------------
__global__ __launch_bounds__(256) void k1_precompute(
    const float* __restrict__ emb_table, const int* __restrict__ target,
    const float* __restrict__ wihf, const float* __restrict__ bihf, const float* __restrict__ bhhf,
    const float* __restrict__ wihb, const float* __restrict__ bihb, const float* __restrict__ bhhb)
{
    __shared__ float se[32][EMB];
    const int tblk = blockIdx.x * 32;
    const int rblk = blockIdx.y * 128;

    for (int i = threadIdx.x; i < 32 * EMB; i += 256) {
        int tt = i >> 8;
        int k  = i & 255;
        int t  = tblk + tt;
        int tok = (t == 0) ? 0 : target[t - 1];   // teacher forcing, SOS=0
        se[tt][k] = emb_table[(size_t)tok * EMB + k];
    }
    __syncthreads();

    const int row_l = threadIdx.x & 127;
    const int th    = threadIdx.x >> 7;
    const int row   = rblk + row_l;

    const float* w;
    float bias;
    if (row < 1024) { w = wihf + (size_t)row * EMB;               bias = bihf[row] + bhhf[row]; }
    else            { int r2 = row - 1024; w = wihb + (size_t)r2 * EMB; bias = bihb[r2] + bhhb[r2]; }

    float acc[16];
#pragma unroll
    for (int i = 0; i < 16; i++) acc[i] = 0.f;

    for (int k = 0; k < EMB; k += 4) {
        float4 wv = *(const float4*)(w + k);
#pragma unroll
        for (int i = 0; i < 16; i++) {
            float4 e = *(const float4*)&se[th * 16 + i][k];
            acc[i] += wv.x * e.x + wv.y * e.y + wv.z * e.z + wv.w * e.w;
        }
    }
#pragma unroll
    for (int i = 0; i < 16; i++) {
        int t = tblk + th * 16 + i;
        g_X[t * NROW + row] = acc[i] + bias;
    }
}

// ---------------------------------------------------------------------------
// Mega kernel: bids 0-15 = R8-proven recurrence (+ g_scnt publish);
// bids 16-127 = workers: per-M-chunk GEMM (work-stolen tiles) + log-softmax
// fixup (work-stolen rows). Workers wait on the recurrence, NEVER vice versa,
// and no worker waits on a specific worker -> deadlock-free by construction.
// ---------------------------------------------------------------------------
#define KPAD 40

__global__ void __cluster_dims__(8, 1, 1) __launch_bounds__(256, 1)
kmega(const float* __restrict__ whhf, const float* __restrict__ whhb,
      float* __restrict__ out_seq, float* __restrict__ out_pv,
      const float* __restrict__ testw, const float* __restrict__ testb)
{
    __shared__ __align__(16) char SMBUF[43008];
    __shared__ int s_job;
    const int bid = blockIdx.x;
    const int tid = threadIdx.x;

    if (bid < 16) {
        // ================= recurrence (R8 body + progress hooks) ============
        float (*sh_h)[264] = (float(*)[264])SMBUF;
        unsigned long long* mbarr = (unsigned long long*)(SMBUF + 2112);

        uint32_t rank;
        asm("mov.u32 %0, %%cluster_ctarank;" : "=r"(rank));
        const int cell = bid >> 3;
        const float* whh = cell ? whhb : whhf;

        const int l     = tid & 31;
        const int wrp   = tid >> 5;
        const int v     = wrp * 4 + (l >> 3);
        const int g     = (l >> 1) & 3;
        const int khalf = l & 1;
        const int d     = l & 7;
        const int unit  = (int)rank * 32 + v;
        const int grow  = g * 256 + unit;

        unsigned long long w[64];
        {
            const float2* wp = (const float2*)(whh + (size_t)grow * HID + khalf * 128);
#pragma unroll
            for (int j = 0; j < 64; j++) {
                float2 x = wp[j];
                asm("mov.b64 %0, {%1, %2};" : "=l"(w[j]) : "f"(x.x), "f"(x.y));
            }
        }

        const uint32_t mb0 = smem_u32(&mbarr[0]);
        const uint32_t mb1 = smem_u32(&mbarr[1]);
        for (int i = tid; i < 528; i += 256) ((float*)sh_h)[i] = 0.f;
        if (tid == 0) {
            asm volatile("mbarrier.init.shared.b64 [%0], %1;" :: "r"(mb0), "r"(1u) : "memory");
            asm volatile("mbarrier.init.shared.b64 [%0], %1;" :: "r"(mb1), "r"(1u) : "memory");
            asm volatile("fence.mbarrier_init.release.cluster;" ::: "memory");
            asm volatile("mbarrier.arrive.expect_tx.shared.b64 _, [%0], %1;" :: "r"(mb0), "r"(1024u) : "memory");
            asm volatile("mbarrier.arrive.expect_tx.shared.b64 _, [%0], %1;" :: "r"(mb1), "r"(1024u) : "memory");
        }
        __syncthreads();
        asm volatile("barrier.cluster.arrive.aligned;" ::: "memory");
        asm volatile("barrier.cluster.wait.aligned;"   ::: "memory");

        const int pos = unit + ((unit >> 7) << 2);
        uint32_t ra0, ra1, rm0, rm1;
        {
            uint32_t la0 = smem_u32(&sh_h[0][pos]);
            uint32_t la1 = smem_u32(&sh_h[1][pos]);
            asm("mapa.shared::cluster.u32 %0, %1, %2;" : "=r"(ra0) : "r"(la0), "r"(d));
            asm("mapa.shared::cluster.u32 %0, %1, %2;" : "=r"(ra1) : "r"(la1), "r"(d));
            asm("mapa.shared::cluster.u32 %0, %1, %2;" : "=r"(rm0) : "r"(mb0), "r"(d));
            asm("mapa.shared::cluster.u32 %0, %1, %2;" : "=r"(rm1) : "r"(mb1), "r"(d));
        }

        float c_reg = 0.f;
        const int xrow = cell * 1024 + grow;

        for (int t = 0; t < TLEN; t++) {
            const int p = t & 1;
            float xv = __ldg(&g_X[t * NROW + xrow]);

            if (t > 0) {
                uint32_t mb = p ? mb1 : mb0;
                mbar_wait(mb, (uint32_t)(((t - 1) >> 1) & 1));
                if (tid == 0)
                    asm volatile("mbarrier.arrive.expect_tx.shared.b64 _, [%0], %1;"
                                 :: "r"(mb), "r"(1024u) : "memory");
            }

            const ulonglong2* hp = (const ulonglong2*)&sh_h[p][khalf * 132];
            unsigned long long a0 = 0ULL, a1 = 0ULL, a2 = 0ULL, a3 = 0ULL;
#pragma unroll
            for (int j = 0; j < 32; j += 2) {
                ulonglong2 v0 = hp[j];
                ulonglong2 v1 = hp[j + 1];
                FMA2(a0, w[2 * j + 0], v0.x);
                FMA2(a1, w[2 * j + 1], v0.y);
                FMA2(a2, w[2 * j + 2], v1.x);
                FMA2(a3, w[2 * j + 3], v1.y);
            }
            float lo0, hi0, lo1, hi1, lo2, hi2, lo3, hi3;
            asm("mov.b64 {%0, %1}, %2;" : "=f"(lo0), "=f"(hi0) : "l"(a0));
            asm("mov.b64 {%0, %1}, %2;" : "=f"(lo1), "=f"(hi1) : "l"(a1));
            asm("mov.b64 {%0, %1}, %2;" : "=f"(lo2), "=f"(hi2) : "l"(a2));
            asm("mov.b64 {%0, %1}, %2;" : "=f"(lo3), "=f"(hi3) : "l"(a3));
            float sum = ((lo0 + hi0) + (lo1 + hi1)) + ((lo2 + hi2) + (lo3 + hi3));
            sum += __shfl_xor_sync(0xffffffffu, sum, 1);
            float z = sum + xv;

            float act = (g == 2) ? ftanh(z) : fsig(z);
            const int base = l & ~7;
            float gi = __shfl_sync(0xffffffffu, act, base + 0);
            float gf = __shfl_sync(0xffffffffu, act, base + 2);
            float gg = __shfl_sync(0xffffffffu, act, base + 4);
            float go = __shfl_sync(0xffffffffu, act, base + 6);
            c_reg = gf * c_reg + gi * gg;
            float hv = go * ftanh(c_reg);

            if (t < TLEN - 1) {
                uint32_t ra = ((t + 1) & 1) ? ra1 : ra0;
                uint32_t rm = ((t + 1) & 1) ? rm1 : rm0;
                asm volatile(
                    "st.async.shared::cluster.mbarrier::complete_tx::bytes.f32 [%0], %1, [%2];"
                    :: "r"(ra), "f"(hv), "r"(rm) : "memory");
            }

            const int lg = l & 7;
            if (cell == 0) {
                if (lg == 1) out_seq[t * 512 + unit] = hv;
                else if (lg == 2) g_S[t * 512 + unit] = hv;
                else if (lg == 3) g_S[t * 512 + 256 + unit] = c_reg;
            } else {
                if (lg == 1) out_seq[t * 512 + 256 + unit] = hv;
            }

            // publish S-chunk progress (cell0 only): 8 CTAs x 8 warps = 64
            if (cell == 0 && (t & 127) == 127) {
                __threadfence();
                __syncwarp();
                if (l == 0) atomicAdd(&g_scnt[t >> 7], 1u);
            }
        }
        return;
    }

    // ==================== worker path ======================================
    __nv_bfloat16 (*sA)[128][KPAD] = (__nv_bfloat16(*)[128][KPAD])(SMBUF);
    __nv_bfloat16 (*sB)[128][KPAD] = (__nv_bfloat16(*)[128][KPAD])(SMBUF + 20480);
    float (*sred)[4]               = (float(*)[4])(SMBUF + 40960);
    float* red                     = (float*)SMBUF;

    const int lrow  = tid >> 1;
    const int lhalf = tid & 1;
    const int warp  = tid >> 5, lane = tid & 31;
    const int wm = warp >> 2, wn = warp & 3;
    const int gq = lane >> 2, tg = lane & 3;

    for (int m = 0; m < 4; m++) {
        // wait for this chunk's g_S rows (published by the recurrence)
        if (tid == 0) {
            volatile unsigned* sc = (volatile unsigned*)g_scnt;
            while (sc[m] < 64u) __nanosleep(256);
        }
        __syncthreads();
        __threadfence();
        const int Mb = m * 128;

        // ---- GEMM tiles, work-stolen ----
        for (;;) {
            __syncthreads();
            if (tid == 0) s_job = (int)atomicAdd(&g_tq[m], 1u);
            __syncthreads();
            const int nbq = s_job;
            if (nbq >= 250) break;
            const int Nb = nbq * 128;

            float acc[4][4][4];
#pragma unroll
            for (int a = 0; a < 4; a++)
#pragma unroll
                for (int b = 0; b < 4; b++)
#pragma unroll
                    for (int c = 0; c < 4; c++) acc[a][b][c] = 0.f;

            const float* Aptr = g_S   + (size_t)(Mb + lrow) * 512 + lhalf * 16;
            const float* Bptr = testw + (size_t)(Nb + lrow) * 512 + lhalf * 16;

            float4 ra[4], rb[4];
#pragma unroll
            for (int q = 0; q < 4; q++) {
                ra[q] = *(const float4*)(Aptr + q * 4);
                rb[q] = *(const float4*)(Bptr + q * 4);
            }
#define STORE_STAGE(buf)                                                                     \
            do {                                                                             \
                _Pragma("unroll")                                                            \
                for (int q = 0; q < 4; q++) {                                                \
                    int c = lhalf * 16 + q * 4;                                              \
                    *(__nv_bfloat162*)&sA[buf][lrow][c]     = __floats2bfloat162_rn(ra[q].x, ra[q].y); \
                    *(__nv_bfloat162*)&sA[buf][lrow][c + 2] = __floats2bfloat162_rn(ra[q].z, ra[q].w); \
                    *(__nv_bfloat162*)&sB[buf][lrow][c]     = __floats2bfloat162_rn(rb[q].x, rb[q].y); \
                    *(__nv_bfloat162*)&sB[buf][lrow][c + 2] = __floats2bfloat162_rn(rb[q].z, rb[q].w); \
                }                                                                            \
            } while (0)
            STORE_STAGE(0);
            __syncthreads();

            for (int kt = 0; kt < 16; kt++) {
                const int cur = kt & 1;
                if (kt < 15) {
#pragma unroll
                    for (int q = 0; q < 4; q++) {
                        ra[q] = *(const float4*)(Aptr + (kt + 1) * 32 + q * 4);
                        rb[q] = *(const float4*)(Bptr + (kt + 1) * 32 + q * 4);
                    }
                }
#pragma unroll
                for (int kk = 0; kk < 32; kk += 16) {
                    uint32_t af[4][4], bf[4][2];
#pragma unroll
                    for (int mt = 0; mt < 4; mt++) {
                        int r0 = wm * 64 + mt * 16 + gq;
                        af[mt][0] = *(const uint32_t*)&sA[cur][r0][kk + tg * 2];
                        af[mt][1] = *(const uint32_t*)&sA[cur][r0 + 8][kk + tg * 2];
                        af[mt][2] = *(const uint32_t*)&sA[cur][r0][kk + tg * 2 + 8];
                        af[mt][3] = *(const uint32_t*)&sA[cur][r0 + 8][kk + tg * 2 + 8];
                    }
#pragma unroll
                    for (int nt = 0; nt < 4; nt++) {
                        int c0 = wn * 32 + nt * 8 + gq;
                        bf[nt][0] = *(const uint32_t*)&sB[cur][c0][kk + tg * 2];
                        bf[nt][1] = *(const uint32_t*)&sB[cur][c0][kk + tg * 2 + 8];
                    }
#pragma unroll
                    for (int mt = 0; mt < 4; mt++)
#pragma unroll
                        for (int nt = 0; nt < 4; nt++) {
                            asm("mma.sync.aligned.m16n8k16.row.col.f32.bf16.bf16.f32 "
                                "{%0,%1,%2,%3}, {%4,%5,%6,%7}, {%8,%9}, {%0,%1,%2,%3};"
                                : "+f"(acc[mt][nt][0]), "+f"(acc[mt][nt][1]),
                                  "+f"(acc[mt][nt][2]), "+f"(acc[mt][nt][3])
                                : "r"(af[mt][0]), "r"(af[mt][1]), "r"(af[mt][2]), "r"(af[mt][3]),
                                  "r"(bf[nt][0]), "r"(bf[nt][1]));
                        }
                }
                if (kt < 15) STORE_STAGE(cur ^ 1);
                __syncthreads();
            }
#undef STORE_STAGE

            float esum[8];
#pragma unroll
            for (int i = 0; i < 8; i++) esum[i] = 0.f;
#pragma unroll
            for (int nt = 0; nt < 4; nt++) {
                int n = Nb + wn * 32 + nt * 8 + tg * 2;
                float2 tb2 = *(const float2*)(testb + n);
#pragma unroll
                for (int mt = 0; mt < 4; mt++) {
                    int m0 = Mb + wm * 64 + mt * 16 + gq;
                    float2 v0 = make_float2(acc[mt][nt][0] + tb2.x, acc[mt][nt][1] + tb2.y);
                    float2 v1 = make_float2(acc[mt][nt][2] + tb2.x, acc[mt][nt][3] + tb2.y);
                    *(float2*)&out_pv[(size_t)m0 * VOC + n] = v0;
                    *(float2*)&out_pv[(size_t)(m0 + 8) * VOC + n] = v1;
                    esum[mt * 2 + 0] += __expf(v0.x) + __expf(v0.y);
                    esum[mt * 2 + 1] += __expf(v1.x) + __expf(v1.y);
                }
            }
#pragma unroll
            for (int i = 0; i < 8; i++) {
                esum[i] += __shfl_xor_sync(0xffffffffu, esum[i], 1);
                esum[i] += __shfl_xor_sync(0xffffffffu, esum[i], 2);
            }
            if (tg == 0) {
#pragma unroll
                for (int mt = 0; mt < 4; mt++) {
                    sred[wm * 64 + mt * 16 + gq][wn]     = esum[mt * 2 + 0];
                    sred[wm * 64 + mt * 16 + gq + 8][wn] = esum[mt * 2 + 1];
                }
            }
            __syncthreads();
            if (tid < 128) {
                float s = sred[tid][0] + sred[tid][1] + sred[tid][2] + sred[tid][3];
                g_part[(size_t)(Mb + tid) * 256 + nbq] = s;
            }
            __threadfence();
            __syncthreads();
            if (tid == 0) atomicAdd(&g_tcnt[m], 1u);
        }

        // ---- wait all tiles of this chunk (completed by resident workers) ----
        if (tid == 0) {
            volatile unsigned* tc = (volatile unsigned*)g_tcnt;
            while (tc[m] < 250u) __nanosleep(256);
        }
        __syncthreads();
        __threadfence();

        // ---- fixup rows, work-stolen ----
        for (;;) {
            __syncthreads();
            if (tid == 0) s_job = (int)atomicAdd(&g_rq[m], 1u);
            __syncthreads();
            const int rr = s_job;
            if (rr >= 128) break;
            const int row = Mb + rr;
            float vv = (tid < 250) ? g_part[(size_t)row * 256 + tid] : 0.f;
            red[tid] = vv;
            __syncthreads();
#pragma unroll
            for (int s = 128; s > 0; s >>= 1) {
                if (tid < s) red[tid] += red[tid + s];
                __syncthreads();
            }
            const float logz = logf(red[0]);
            __syncthreads();
            float4* rp = (float4*)(out_pv + (size_t)row * VOC);
            for (int i = tid; i < VOC / 4; i += 256) {
                float4 x = rp[i];
                x.x -= logz; x.y -= logz; x.z -= logz; x.w -= logz;
                rp[i] = x;
            }
        }
    }
}

// ---------------------------------------------------------------------------
extern "C" void kernel_launch(void* const* d_in, const int* in_sizes, int n_in,
                              void* d_out, int out_size)
{
    const float* emb   = (const float*)d_in[1];
    const float* wihf  = (const float*)d_in[2];
    const float* whhf  = (const float*)d_in[3];
    const float* bihf  = (const float*)d_in[4];
    const float* bhhf  = (const float*)d_in[5];
    const float* wihb  = (const float*)d_in[6];
    const float* whhb  = (const float*)d_in[7];
    const float* bihb  = (const float*)d_in[8];
    const float* bhhb  = (const float*)d_in[9];
    const float* testw = (const float*)d_in[20];
    const float* testb = (const float*)d_in[21];
    const int*   tgt   = (const int*)d_in[22];

    float* out_pv  = (float*)d_out;                       // Pvocab [512, 1, 32000]
    float* out_seq = out_pv + (size_t)TLEN * VOC;         // outputs [512, 512]

    k1_precompute<<<dim3(16, 16), 256>>>(emb, tgt, wihf, bihf, bhhf, wihb, bihb, bhhb);
    kreset<<<1, 32>>>();
    knop1<<<1, 32>>>();                                   // ncu slot -> kmega (idx 3)
    kmega<<<16 + NWORK, 256>>>(whhf, whhb, out_seq, out_pv, testw, testb);
}

// round 15
// speedup vs baseline: 1.0498x; 1.0018x over previous
#include <cuda_runtime.h>
#include <cuda_bf16.h>
#include <cstdint>

#define TLEN 512
#define HID  256
#define EMB  256
#define VOC  32000
#define NROW 2048   // 2 cells * 4H gate rows
#define NWORK 112   // worker CTAs (bids 16..127)
#define NCHUNK 8    // 8 chunks x 64 steps
#define CROWS 64    // rows per chunk (worker BM)

// Scratch (static device globals — no runtime allocation; zero-initialized)
__device__ float g_X[TLEN * NROW];           // 4 MB   precomputed x@W_ih^T + biases
__device__ float g_S[TLEN * 2 * HID];        // 1 MB   s_t = [hf, cf]
__device__ float g_part[TLEN * 256];         // per-(row, colblock) sumexp partials (cols 250-255 stay 0)
__device__ unsigned g_scnt[NCHUNK];          // S progress per chunk (target 64 warp-arrivals)
__device__ unsigned g_tq[NCHUNK];            // GEMM tile queue per chunk (take while < 250)
__device__ unsigned g_tcnt[NCHUNK];          // GEMM tiles completed per chunk (target 250)
__device__ unsigned g_rq[NCHUNK];            // fixup row queue per chunk (take while < CROWS)

__device__ __forceinline__ uint32_t smem_u32(const void* p) {
    return (uint32_t)__cvta_generic_to_shared(p);
}

__device__ __forceinline__ float fast_ex2(float x) {
    float r; asm("ex2.approx.f32 %0, %1;" : "=f"(r) : "f"(x)); return r;
}
__device__ __forceinline__ float fast_rcp(float x) {
    float r; asm("rcp.approx.f32 %0, %1;" : "=f"(r) : "f"(x)); return r;
}
__device__ __forceinline__ float fsig(float x) {
    return fast_rcp(1.f + fast_ex2(-1.4426950408889634f * x));
}
__device__ __forceinline__ float ftanh(float x) {
    return 1.f - 2.f * fast_rcp(1.f + fast_ex2(2.8853900817779268f * x));
}

#define FMA2(acc, a, b) asm("fma.rn.f32x2 %0, %1, %2, %0;" : "+l"(acc) : "l"(a), "l"(b))

__device__ __forceinline__ void mbar_wait(uint32_t mbar, uint32_t par) {
    asm volatile(
        "{\n\t.reg .pred P;\n\t"
        "WAITLP_%=:\n\t"
        "mbarrier.try_wait.parity.acquire.cta.shared::cta.b64 P, [%0], %1, 0x989680;\n\t"
        "@P bra.uni WAITDN_%=;\n\t"
        "bra.uni WAITLP_%=;\n\t"
        "WAITDN_%=:\n\t}"
        :: "r"(mbar), "r"(par) : "memory");
}

// ---------------------------------------------------------------------------
__global__ void kreset() {
    if (threadIdx.x < NCHUNK) {
        g_scnt[threadIdx.x] = 0;
        g_tq[threadIdx.x] = 0;
        g_tcnt[threadIdx.x] = 0;
        g_rq[threadIdx.x] = 0;
    }
}
__global__ void knop1() {}

// ---------------------------------------------------------------------------
// K1: X[t][row] = emb[token_t] . w_ih[row] + b_ih[row] + b_hh[row]
// (separate kernel BEFORE the mega: the recurrence never waits on workers)
// ---------------------------------------------------------------------------
__global__ __launch_bounds__(256) void k1_precompute(
    const float* __restrict__ emb_table, const int* __restrict__ target,
    const float* __restrict__ wihf, const float* __restrict__ bihf, const float* __restrict__ bhhf,
    const float* __restrict__ wihb, const float* __restrict__ bihb, const float* __restrict__ bhhb)
{
    __shared__ float se[32][EMB];
    const int tblk = blockIdx.x * 32;
    const int rblk = blockIdx.y * 128;

    for (int i = threadIdx.x; i < 32 * EMB; i += 256) {
        int tt = i >> 8;
        int k  = i & 255;
        int t  = tblk + tt;
        int tok = (t == 0) ? 0 : target[t - 1];   // teacher forcing, SOS=0
        se[tt][k] = emb_table[(size_t)tok * EMB + k];
    }
    __syncthreads();

    const int row_l = threadIdx.x & 127;
    const int th    = threadIdx.x >> 7;
    const int row   = rblk + row_l;

    const float* w;
    float bias;
    if (row < 1024) { w = wihf + (size_t)row * EMB;               bias = bihf[row] + bhhf[row]; }
    else            { int r2 = row - 1024; w = wihb + (size_t)r2 * EMB; bias = bihb[r2] + bhhb[r2]; }

    float acc[16];
#pragma unroll
    for (int i = 0; i < 16; i++) acc[i] = 0.f;

    for (int k = 0; k < EMB; k += 4) {
        float4 wv = *(const float4*)(w + k);
#pragma unroll
        for (int i = 0; i < 16; i++) {
            float4 e = *(const float4*)&se[th * 16 + i][k];
            acc[i] += wv.x * e.x + wv.y * e.y + wv.z * e.z + wv.w * e.w;
        }
    }
#pragma unroll
    for (int i = 0; i < 16; i++) {
        int t = tblk + th * 16 + i;
        g_X[t * NROW + row] = acc[i] + bias;
    }
}

// ---------------------------------------------------------------------------
// Mega kernel: bids 0-15 = R8-proven recurrence (+ g_scnt publish per 64
// steps); bids 16-127 = workers: per-chunk 64x128 GEMM tiles (work-stolen)
// + log-softmax fixup (work-stolen rows). Deadlock-free by construction.
// ---------------------------------------------------------------------------
#define KPAD 40

__global__ void __cluster_dims__(8, 1, 1) __launch_bounds__(256, 1)
kmega(const float* __restrict__ whhf, const float* __restrict__ whhb,
      float* __restrict__ out_seq, float* __restrict__ out_pv,
      const float* __restrict__ testw, const float* __restrict__ testb)
{
    __shared__ __align__(16) char SMBUF[32768];
    __shared__ int s_job;
    const int bid = blockIdx.x;
    const int tid = threadIdx.x;

    if (bid < 16) {
        // ================= recurrence (R8 body + progress hooks) ============
        float (*sh_h)[264] = (float(*)[264])SMBUF;
        unsigned long long* mbarr = (unsigned long long*)(SMBUF + 2112);

        uint32_t rank;
        asm("mov.u32 %0, %%cluster_ctarank;" : "=r"(rank));
        const int cell = bid >> 3;
        const float* whh = cell ? whhb : whhf;

        const int l     = tid & 31;
        const int wrp   = tid >> 5;
        const int v     = wrp * 4 + (l >> 3);
        const int g     = (l >> 1) & 3;
        const int khalf = l & 1;
        const int d     = l & 7;
        const int unit  = (int)rank * 32 + v;
        const int grow  = g * 256 + unit;

        unsigned long long w[64];
        {
            const float2* wp = (const float2*)(whh + (size_t)grow * HID + khalf * 128);
#pragma unroll
            for (int j = 0; j < 64; j++) {
                float2 x = wp[j];
                asm("mov.b64 %0, {%1, %2};" : "=l"(w[j]) : "f"(x.x), "f"(x.y));
            }
        }

        const uint32_t mb0 = smem_u32(&mbarr[0]);
        const uint32_t mb1 = smem_u32(&mbarr[1]);
        for (int i = tid; i < 528; i += 256) ((float*)sh_h)[i] = 0.f;
        if (tid == 0) {
            asm volatile("mbarrier.init.shared.b64 [%0], %1;" :: "r"(mb0), "r"(1u) : "memory");
            asm volatile("mbarrier.init.shared.b64 [%0], %1;" :: "r"(mb1), "r"(1u) : "memory");
            asm volatile("fence.mbarrier_init.release.cluster;" ::: "memory");
            asm volatile("mbarrier.arrive.expect_tx.shared.b64 _, [%0], %1;" :: "r"(mb0), "r"(1024u) : "memory");
            asm volatile("mbarrier.arrive.expect_tx.shared.b64 _, [%0], %1;" :: "r"(mb1), "r"(1024u) : "memory");
        }
        __syncthreads();
        asm volatile("barrier.cluster.arrive.aligned;" ::: "memory");
        asm volatile("barrier.cluster.wait.aligned;"   ::: "memory");

        const int pos = unit + ((unit >> 7) << 2);
        uint32_t ra0, ra1, rm0, rm1;
        {
            uint32_t la0 = smem_u32(&sh_h[0][pos]);
            uint32_t la1 = smem_u32(&sh_h[1][pos]);
            asm("mapa.shared::cluster.u32 %0, %1, %2;" : "=r"(ra0) : "r"(la0), "r"(d));
            asm("mapa.shared::cluster.u32 %0, %1, %2;" : "=r"(ra1) : "r"(la1), "r"(d));
            asm("mapa.shared::cluster.u32 %0, %1, %2;" : "=r"(rm0) : "r"(mb0), "r"(d));
            asm("mapa.shared::cluster.u32 %0, %1, %2;" : "=r"(rm1) : "r"(mb1), "r"(d));
        }

        float c_reg = 0.f;
        const int xrow = cell * 1024 + grow;

        for (int t = 0; t < TLEN; t++) {
            const int p = t & 1;
            float xv = __ldg(&g_X[t * NROW + xrow]);

            if (t > 0) {
                uint32_t mb = p ? mb1 : mb0;
                mbar_wait(mb, (uint32_t)(((t - 1) >> 1) & 1));
                if (tid == 0)
                    asm volatile("mbarrier.arrive.expect_tx.shared.b64 _, [%0], %1;"
                                 :: "r"(mb), "r"(1024u) : "memory");
            }

            const ulonglong2* hp = (const ulonglong2*)&sh_h[p][khalf * 132];
            unsigned long long a0 = 0ULL, a1 = 0ULL, a2 = 0ULL, a3 = 0ULL;
#pragma unroll
            for (int j = 0; j < 32; j += 2) {
                ulonglong2 v0 = hp[j];
                ulonglong2 v1 = hp[j + 1];
                FMA2(a0, w[2 * j + 0], v0.x);
                FMA2(a1, w[2 * j + 1], v0.y);
                FMA2(a2, w[2 * j + 2], v1.x);
                FMA2(a3, w[2 * j + 3], v1.y);
            }
            float lo0, hi0, lo1, hi1, lo2, hi2, lo3, hi3;
            asm("mov.b64 {%0, %1}, %2;" : "=f"(lo0), "=f"(hi0) : "l"(a0));
            asm("mov.b64 {%0, %1}, %2;" : "=f"(lo1), "=f"(hi1) : "l"(a1));
            asm("mov.b64 {%0, %1}, %2;" : "=f"(lo2), "=f"(hi2) : "l"(a2));
            asm("mov.b64 {%0, %1}, %2;" : "=f"(lo3), "=f"(hi3) : "l"(a3));
            float sum = ((lo0 + hi0) + (lo1 + hi1)) + ((lo2 + hi2) + (lo3 + hi3));
            sum += __shfl_xor_sync(0xffffffffu, sum, 1);
            float z = sum + xv;

            float act = (g == 2) ? ftanh(z) : fsig(z);
            const int base = l & ~7;
            float gi = __shfl_sync(0xffffffffu, act, base + 0);
            float gf = __shfl_sync(0xffffffffu, act, base + 2);
            float gg = __shfl_sync(0xffffffffu, act, base + 4);
            float go = __shfl_sync(0xffffffffu, act, base + 6);
            c_reg = gf * c_reg + gi * gg;
            float hv = go * ftanh(c_reg);

            if (t < TLEN - 1) {
                uint32_t ra = ((t + 1) & 1) ? ra1 : ra0;
                uint32_t rm = ((t + 1) & 1) ? rm1 : rm0;
                asm volatile(
                    "st.async.shared::cluster.mbarrier::complete_tx::bytes.f32 [%0], %1, [%2];"
                    :: "r"(ra), "f"(hv), "r"(rm) : "memory");
            }

            const int lg = l & 7;
            if (cell == 0) {
                if (lg == 1) out_seq[t * 512 + unit] = hv;
                else if (lg == 2) g_S[t * 512 + unit] = hv;
                else if (lg == 3) g_S[t * 512 + 256 + unit] = c_reg;
            } else {
                if (lg == 1) out_seq[t * 512 + 256 + unit] = hv;
            }

            // publish S-chunk progress (cell0 only): 8 CTAs x 8 warps = 64
            if (cell == 0 && (t & 63) == 63) {
                __threadfence();
                __syncwarp();
                if (l == 0) atomicAdd(&g_scnt[t >> 6], 1u);
            }
        }
        return;
    }

    // ==================== worker path ======================================
    // tiles: 64 (M) x 128 (N) x 512 (K), double-buffered bf16 staging
    __nv_bfloat16 (*sA)[CROWS][KPAD] = (__nv_bfloat16(*)[CROWS][KPAD])(SMBUF);            // 2*64*40*2  = 10240
    __nv_bfloat16 (*sB)[128][KPAD]   = (__nv_bfloat16(*)[128][KPAD])(SMBUF + 10240);      // 2*128*40*2 = 20480
    float (*sred)[4]                 = (float(*)[4])(SMBUF + 30720);                      // 64*4*4     = 1024
    float* red                       = (float*)SMBUF;

    const int lrow  = tid >> 1;
    const int lhalf = tid & 1;
    const int warp  = tid >> 5, lane = tid & 31;
    const int wm = warp >> 2, wn = warp & 3;
    const int gq = lane >> 2, tg = lane & 3;

    for (int m = 0; m < NCHUNK; m++) {
        if (tid == 0) {
            volatile unsigned* sc = (volatile unsigned*)g_scnt;
            while (sc[m] < 64u) __nanosleep(256);
        }
        __syncthreads();
        __threadfence();
        const int Mb = m * CROWS;

        // ---- GEMM tiles, work-stolen ----
        for (;;) {
            __syncthreads();
            if (tid == 0) s_job = (int)atomicAdd(&g_tq[m], 1u);
            __syncthreads();
            const int nbq = s_job;
            if (nbq >= 250) break;
            const int Nb = nbq * 128;

            float acc[2][4][4];
#pragma unroll
            for (int a = 0; a < 2; a++)
#pragma unroll
                for (int b = 0; b < 4; b++)
#pragma unroll
                    for (int c = 0; c < 4; c++) acc[a][b][c] = 0.f;

            const float* Aptr = g_S   + (size_t)(Mb + lrow) * 512 + lhalf * 16;   // lrow<64 only
            const float* Bptr = testw + (size_t)(Nb + lrow) * 512 + lhalf * 16;

            float4 ra[4], rb[4];
#pragma unroll
            for (int q = 0; q < 4; q++) {
                if (lrow < CROWS) ra[q] = *(const float4*)(Aptr + q * 4);
                rb[q] = *(const float4*)(Bptr + q * 4);
            }
#define STORE_STAGE(buf)                                                                     \
            do {                                                                             \
                _Pragma("unroll")                                                            \
                for (int q = 0; q < 4; q++) {                                                \
                    int c = lhalf * 16 + q * 4;                                              \
                    if (lrow < CROWS) {                                                      \
                        *(__nv_bfloat162*)&sA[buf][lrow][c]     = __floats2bfloat162_rn(ra[q].x, ra[q].y); \
                        *(__nv_bfloat162*)&sA[buf][lrow][c + 2] = __floats2bfloat162_rn(ra[q].z, ra[q].w); \
                    }                                                                        \
                    *(__nv_bfloat162*)&sB[buf][lrow][c]     = __floats2bfloat162_rn(rb[q].x, rb[q].y); \
                    *(__nv_bfloat162*)&sB[buf][lrow][c + 2] = __floats2bfloat162_rn(rb[q].z, rb[q].w); \
                }                                                                            \
            } while (0)
            STORE_STAGE(0);
            __syncthreads();

            for (int kt = 0; kt < 16; kt++) {
                const int cur = kt & 1;
                if (kt < 15) {
#pragma unroll
                    for (int q = 0; q < 4; q++) {
                        if (lrow < CROWS) ra[q] = *(const float4*)(Aptr + (kt + 1) * 32 + q * 4);
                        rb[q] = *(const float4*)(Bptr + (kt + 1) * 32 + q * 4);
                    }
                }
#pragma unroll
                for (int kk = 0; kk < 32; kk += 16) {
                    uint32_t af[2][4], bf[4][2];
#pragma unroll
                    for (int mt = 0; mt < 2; mt++) {
                        int r0 = wm * 32 + mt * 16 + gq;
                        af[mt][0] = *(const uint32_t*)&sA[cur][r0][kk + tg * 2];
                        af[mt][1] = *(const uint32_t*)&sA[cur][r0 + 8][kk + tg * 2];
                        af[mt][2] = *(const uint32_t*)&sA[cur][r0][kk + tg * 2 + 8];
                        af[mt][3] = *(const uint32_t*)&sA[cur][r0 + 8][kk + tg * 2 + 8];
                    }
#pragma unroll
                    for (int nt = 0; nt < 4; nt++) {
                        int c0 = wn * 32 + nt * 8 + gq;
                        bf[nt][0] = *(const uint32_t*)&sB[cur][c0][kk + tg * 2];
                        bf[nt][1] = *(const uint32_t*)&sB[cur][c0][kk + tg * 2 + 8];
                    }
#pragma unroll
                    for (int mt = 0; mt < 2; mt++)
#pragma unroll
                        for (int nt = 0; nt < 4; nt++) {
                            asm("mma.sync.aligned.m16n8k16.row.col.f32.bf16.bf16.f32 "
                                "{%0,%1,%2,%3}, {%4,%5,%6,%7}, {%8,%9}, {%0,%1,%2,%3};"
                                : "+f"(acc[mt][nt][0]), "+f"(acc[mt][nt][1]),
                                  "+f"(acc[mt][nt][2]), "+f"(acc[mt][nt][3])
                                : "r"(af[mt][0]), "r"(af[mt][1]), "r"(af[mt][2]), "r"(af[mt][3]),
                                  "r"(bf[nt][0]), "r"(bf[nt][1]));
                        }
                }
                if (kt < 15) STORE_STAGE(cur ^ 1);
                __syncthreads();
            }
#undef STORE_STAGE

            float esum[4];
#pragma unroll
            for (int i = 0; i < 4; i++) esum[i] = 0.f;
#pragma unroll
            for (int nt = 0; nt < 4; nt++) {
                int n = Nb + wn * 32 + nt * 8 + tg * 2;
                float2 tb2 = *(const float2*)(testb + n);
#pragma unroll
                for (int mt = 0; mt < 2; mt++) {
                    int m0 = Mb + wm * 32 + mt * 16 + gq;
                    float2 v0 = make_float2(acc[mt][nt][0] + tb2.x, acc[mt][nt][1] + tb2.y);
                    float2 v1 = make_float2(acc[mt][nt][2] + tb2.x, acc[mt][nt][3] + tb2.y);
                    *(float2*)&out_pv[(size_t)m0 * VOC + n] = v0;
                    *(float2*)&out_pv[(size_t)(m0 + 8) * VOC + n] = v1;
                    esum[mt * 2 + 0] += __expf(v0.x) + __expf(v0.y);
                    esum[mt * 2 + 1] += __expf(v1.x) + __expf(v1.y);
                }
            }
#pragma unroll
            for (int i = 0; i < 4; i++) {
                esum[i] += __shfl_xor_sync(0xffffffffu, esum[i], 1);
                esum[i] += __shfl_xor_sync(0xffffffffu, esum[i], 2);
            }
            if (tg == 0) {
#pragma unroll
                for (int mt = 0; mt < 2; mt++) {
                    sred[wm * 32 + mt * 16 + gq][wn]     = esum[mt * 2 + 0];
                    sred[wm * 32 + mt * 16 + gq + 8][wn] = esum[mt * 2 + 1];
                }
            }
            __syncthreads();
            if (tid < CROWS) {
                float s = sred[tid][0] + sred[tid][1] + sred[tid][2] + sred[tid][3];
                g_part[(size_t)(Mb + tid) * 256 + nbq] = s;
            }
            __threadfence();
            __syncthreads();
            if (tid == 0) atomicAdd(&g_tcnt[m], 1u);
        }

        // ---- wait all tiles of this chunk ----
        if (tid == 0) {
            volatile unsigned* tc = (volatile unsigned*)g_tcnt;
            while (tc[m] < 250u) __nanosleep(256);
        }
        __syncthreads();
        __threadfence();

        // ---- fixup rows, work-stolen ----
        for (;;) {
            __syncthreads();
            if (tid == 0) s_job = (int)atomicAdd(&g_rq[m], 1u);
            __syncthreads();
            const int rr = s_job;
            if (rr >= CROWS) break;
            const int row = Mb + rr;
            float vv = (tid < 250) ? g_part[(size_t)row * 256 + tid] : 0.f;
            red[tid] = vv;
            __syncthreads();
#pragma unroll
            for (int s = 128; s > 0; s >>= 1) {
                if (tid < s) red[tid] += red[tid + s];
                __syncthreads();
            }
            const float logz = logf(red[0]);
            __syncthreads();
            float4* rp = (float4*)(out_pv + (size_t)row * VOC);
            for (int i = tid; i < VOC / 4; i += 256) {
                float4 x = rp[i];
                x.x -= logz; x.y -= logz; x.z -= logz; x.w -= logz;
                rp[i] = x;
            }
        }
    }
}

// ---------------------------------------------------------------------------
extern "C" void kernel_launch(void* const* d_in, const int* in_sizes, int n_in,
                              void* d_out, int out_size)
{
    const float* emb   = (const float*)d_in[1];
    const float* wihf  = (const float*)d_in[2];
    const float* whhf  = (const float*)d_in[3];
    const float* bihf  = (const float*)d_in[4];
    const float* bhhf  = (const float*)d_in[5];
    const float* wihb  = (const float*)d_in[6];
    const float* whhb  = (const float*)d_in[7];
    const float* bihb  = (const float*)d_in[8];
    const float* bhhb  = (const float*)d_in[9];
    const float* testw = (const float*)d_in[20];
    const float* testb = (const float*)d_in[21];
    const int*   tgt   = (const int*)d_in[22];

    float* out_pv  = (float*)d_out;                       // Pvocab [512, 1, 32000]
    float* out_seq = out_pv + (size_t)TLEN * VOC;         // outputs [512, 512]

    k1_precompute<<<dim3(16, 16), 256>>>(emb, tgt, wihf, bihf, bhhf, wihb, bihb, bhhb);
    kreset<<<1, 32>>>();
    knop1<<<1, 32>>>();                                   // ncu slot -> kmega (idx 3)
    kmega<<<16 + NWORK, 256>>>(whhf, whhb, out_seq, out_pv, testw, testb);
}